// round 14
// baseline (speedup 1.0000x reference)
#include <cuda_runtime.h>
#include <cuda_fp16.h>
#include <cstdint>

#define D        512
#define MAXN     50000
#define MAXE     800000
#define SCANB    ((MAXN + 1023) / 1024)   // 49 blocks

// ---------------- device scratch ----------------
__device__ __half g_xh[(size_t)MAXN * D];   // x converted to fp16
__device__ __half g_wh[(size_t)D * D];      // W converted to fp16 [n][k]
__device__ float  g_deg[MAXN];              // source-degree
__device__ int    g_cnt[MAXN];              // col histogram
__device__ int    g_off[MAXN + 1];          // CSC partial offsets (scanA output)
__device__ int    g_cur[MAXN];              // fill cursors
__device__ int2   g_spack[MAXE];            // packed (srow, norm-bits) by destination
__device__ int    g_bsum[SCANB];
__device__ int    g_boff[SCANB];            // per-block exclusive offsets
__device__ int    g_done;                   // scan last-block arrival counter

// ---------------- inline dtype sniff ----------------
__device__ __forceinline__ int sniff_is64(const int* ei32) {
    int lane = threadIdx.x & 31;
    int v = ei32[2 * lane + 1];
    unsigned nz = __ballot_sync(0xffffffffu, v != 0);
    return nz == 0u;
}

__device__ __forceinline__ int load_idx(const void* ei, long long pos, int is64) {
    if (is64) return (int)((const long long*)ei)[pos];
    return ((const int*)ei)[pos];
}

__device__ __forceinline__ int final_off(int i) {
    return (i == 0) ? 0 : (g_off[i] + g_boff[(i - 1) >> 10]);
}

// ---------------- zero small arrays ----------------
__global__ void zero_small_kernel(int n_nodes) {
    int i = blockIdx.x * blockDim.x + threadIdx.x;
    if (i < n_nodes) {
        g_deg[i] = 0.f;
        g_cnt[i] = 0;
        g_cur[i] = 0;
    }
    if (i == 0) g_done = 0;
}

// ---------------- fused histogram + fp16 conversions (block-range split) ----
__global__ void __launch_bounds__(256)
histconv_kernel(const void* __restrict__ ei,
                const float* __restrict__ x,
                const float* __restrict__ W,
                int E, int n_nodes, int eblocks, int convblocks) {
    if ((int)blockIdx.x < eblocks) {
        int is64 = sniff_is64((const int*)ei);
        int e = blockIdx.x * 256 + threadIdx.x;
        if (e >= E) return;
        int r = load_idx(ei, e, is64);
        int c = load_idx(ei, (long long)E + e, is64);
        atomicAdd(&g_deg[r], 1.0f);
        atomicAdd(&g_cnt[c], 1);
    } else {
        size_t t = (size_t)(blockIdx.x - eblocks) * 256 + threadIdx.x;
        size_t stride = (size_t)convblocks * 256;

        size_t wtotal8 = (size_t)D * D / 8;
        for (size_t k = t; k < wtotal8; k += stride) {
            float4 f0 = ((const float4*)W)[2 * k];
            float4 f1 = ((const float4*)W)[2 * k + 1];
            __half2 h0 = __floats2half2_rn(f0.x, f0.y);
            __half2 h1 = __floats2half2_rn(f0.z, f0.w);
            __half2 h2 = __floats2half2_rn(f1.x, f1.y);
            __half2 h3 = __floats2half2_rn(f1.z, f1.w);
            uint4 p;
            p.x = *(uint32_t*)&h0; p.y = *(uint32_t*)&h1;
            p.z = *(uint32_t*)&h2; p.w = *(uint32_t*)&h3;
            ((uint4*)g_wh)[k] = p;
        }

        size_t xtotal8 = (size_t)n_nodes * D / 8;
        for (size_t k = t; k < xtotal8; k += stride) {
            float4 f0 = ((const float4*)x)[2 * k];
            float4 f1 = ((const float4*)x)[2 * k + 1];
            __half2 h0 = __floats2half2_rn(f0.x, f0.y);
            __half2 h1 = __floats2half2_rn(f0.z, f0.w);
            __half2 h2 = __floats2half2_rn(f1.x, f1.y);
            __half2 h3 = __floats2half2_rn(f1.z, f1.w);
            uint4 p;
            p.x = *(uint32_t*)&h0; p.y = *(uint32_t*)&h1;
            p.z = *(uint32_t*)&h2; p.w = *(uint32_t*)&h3;
            ((uint4*)g_xh)[k] = p;
        }
    }
}

// ---------------- scan: phase A per-block + fused phase B in last block -----
__device__ __forceinline__ int block_scan_1024(int v, int* warpsum) {
    const int lane = threadIdx.x & 31;
    const int wid  = threadIdx.x >> 5;
#pragma unroll
    for (int d = 1; d < 32; d <<= 1) {
        int tt = __shfl_up_sync(0xffffffffu, v, d);
        if (lane >= d) v += tt;
    }
    if (lane == 31) warpsum[wid] = v;
    __syncthreads();
    if (wid == 0) {
        int s = warpsum[lane];
#pragma unroll
        for (int d = 1; d < 32; d <<= 1) {
            int tt = __shfl_up_sync(0xffffffffu, s, d);
            if (lane >= d) s += tt;
        }
        warpsum[lane] = s;
    }
    __syncthreads();
    return v + ((wid > 0) ? warpsum[wid - 1] : 0);
}

__global__ void __launch_bounds__(1024)
scanAB_kernel(int n, int nb) {
    __shared__ int warpsum[32];
    __shared__ int is_last;
    int i = blockIdx.x * 1024 + threadIdx.x;
    int v = (i < n) ? g_cnt[i] : 0;
    int incl = block_scan_1024(v, warpsum);
    if (i < n) g_off[i + 1] = incl;
    if (i == 0) g_off[0] = 0;

    if (threadIdx.x == 1023) {
        g_bsum[blockIdx.x] = incl;
        __threadfence();
        int prev = atomicAdd(&g_done, 1);
        is_last = (prev == nb - 1);
    }
    __syncthreads();

    if (is_last) {
        __threadfence();
        int vv = (threadIdx.x < nb) ? g_bsum[threadIdx.x] : 0;
        int inc2 = block_scan_1024(vv, warpsum);
        if (threadIdx.x < nb) g_boff[threadIdx.x] = inc2 - vv;
        if (threadIdx.x == 0) g_done = 0;
    }
}

// ---------------- fused fill (packed int2 store) ----------------
__global__ void fill_kernel(const void* __restrict__ ei,
                            const float* __restrict__ edge_attr,
                            const float* __restrict__ conf_w,
                            const float* __restrict__ conf_b,
                            int E) {
    int is64 = sniff_is64((const int*)ei);
    int e = blockIdx.x * blockDim.x + threadIdx.x;
    if (e >= E) return;
    int r = load_idx(ei, e, is64);
    int c = load_idx(ei, (long long)E + e, is64);

    float z = edge_attr[3 * e + 0] * conf_w[0]
            + edge_attr[3 * e + 1] * conf_w[1]
            + edge_attr[3 * e + 2] * conf_w[2]
            + conf_b[0];
    float ew = 1.0f / (1.0f + expf(-z));

    float dr = g_deg[r];
    float dc = g_deg[c];
    float ir = (dr > 0.f) ? rsqrtf(dr) : 0.f;
    float ic = (dc > 0.f) ? rsqrtf(dc) : 0.f;
    float nrm = ir * ic * ew;
    if (isnan(nrm)) nrm = 0.f;

    int pos = final_off(c) + atomicAdd(&g_cur[c], 1);
    g_spack[pos] = make_int2(r, __float_as_int(nrm));
}

// ---------------- FUSED aggregate + GEMM ----------------
// One block per 128-row M-tile.
// Phase 1: 8 warps aggregate their 16 nodes each -> fp16 A-tile in smem.
// Phase 2: GEMM over 4 N-tiles of 128, B double-buffered via cp.async,
//          A fragments read from resident smem tile.
#define APITCH   520                       // halves per A smem row (512+8); 260 words, 260%32=4
#define KC       32                        // k halves per B chunk
#define HPITCH   40                        // B smem row pitch
#define ASM_B    (128 * APITCH * 2)        // 133120 B
#define BSM_B    (2 * 128 * HPITCH * 2)    // 20480 B
#define FSMEM    (ASM_B + BSM_B)           // 153600 B

__device__ __forceinline__ void cp_async16(uint32_t smem, const void* gptr, int valid) {
    asm volatile("cp.async.cg.shared.global [%0], [%1], 16, %2;\n"
                 :: "r"(smem), "l"(gptr), "r"(valid ? 16 : 0));
}
__device__ __forceinline__ void cp_commit() {
    asm volatile("cp.async.commit_group;\n" ::: "memory");
}
__device__ __forceinline__ void cp_wait1() {
    asm volatile("cp.async.wait_group 1;\n" ::: "memory");
}
__device__ __forceinline__ void cp_wait0() {
    asm volatile("cp.async.wait_group 0;\n" ::: "memory");
}

__device__ __forceinline__ void acc_u4(float2* a, uint4 u, float n) {
    const __half2* h = (const __half2*)&u;
#pragma unroll
    for (int j = 0; j < 4; j++) {
        float2 f = __half22float2(h[j]);
        a[j].x = fmaf(f.x, n, a[j].x);
        a[j].y = fmaf(f.y, n, a[j].y);
    }
}

__global__ void __launch_bounds__(256)
agg_gemm_kernel(const float* __restrict__ bias,
                float* __restrict__ out,
                int Nrows) {
    extern __shared__ __half sdyn[];
    __half* sA  = sdyn;                       // [128][APITCH]
    __half* Bs0 = sA + 128 * APITCH;
    __half* Bs1 = Bs0 + 128 * HPITCH;

    const int tid  = threadIdx.x;
    const int warp = tid >> 5;
    const int lane = tid & 31;
    const int m0   = blockIdx.x * 128;

    // ---------------- Phase 1: aggregate 16 nodes per warp into sA ----------
#pragma unroll 1
    for (int j = 0; j < 16; j++) {
        int rloc = warp * 16 + j;
        int node = m0 + rloc;

        float2 a[8];
#pragma unroll
        for (int q = 0; q < 8; q++) a[q] = make_float2(0.f, 0.f);

        if (node < Nrows) {
            int beg = final_off(node);
            int end = final_off(node + 1);
            int i = beg;
            for (; i + 1 < end; i += 2) {
                int2 pA = g_spack[i];
                int2 pB = g_spack[i + 1];
                float nA = __int_as_float(pA.y);
                float nB = __int_as_float(pB.y);
                const uint4* xA = (const uint4*)(g_xh + (size_t)pA.x * D);
                const uint4* xB = (const uint4*)(g_xh + (size_t)pB.x * D);
                uint4 uA0 = xA[lane];
                uint4 uA1 = xA[lane + 32];
                uint4 uB0 = xB[lane];
                uint4 uB1 = xB[lane + 32];
                acc_u4(a,     uA0, nA);
                acc_u4(a + 4, uA1, nA);
                acc_u4(a,     uB0, nB);
                acc_u4(a + 4, uB1, nB);
            }
            if (i < end) {
                int2 p = g_spack[i];
                float nm = __int_as_float(p.y);
                const uint4* xr = (const uint4*)(g_xh + (size_t)p.x * D);
                uint4 u0 = xr[lane];
                uint4 u1 = xr[lane + 32];
                acc_u4(a,     u0, nm);
                acc_u4(a + 4, u1, nm);
            }
        }

        // pack fp16 and store row into sA (row is 16B aligned: APITCH*2=1040=65*16)
        uint4* dst = (uint4*)(sA + (size_t)rloc * APITCH);
        uint4 o0, o1;
        __half2 t;
        t = __floats2half2_rn(a[0].x, a[0].y); o0.x = *(uint32_t*)&t;
        t = __floats2half2_rn(a[1].x, a[1].y); o0.y = *(uint32_t*)&t;
        t = __floats2half2_rn(a[2].x, a[2].y); o0.z = *(uint32_t*)&t;
        t = __floats2half2_rn(a[3].x, a[3].y); o0.w = *(uint32_t*)&t;
        t = __floats2half2_rn(a[4].x, a[4].y); o1.x = *(uint32_t*)&t;
        t = __floats2half2_rn(a[5].x, a[5].y); o1.y = *(uint32_t*)&t;
        t = __floats2half2_rn(a[6].x, a[6].y); o1.z = *(uint32_t*)&t;
        t = __floats2half2_rn(a[7].x, a[7].y); o1.w = *(uint32_t*)&t;
        dst[lane]      = o0;
        dst[lane + 32] = o1;
    }
    __syncthreads();

    // ---------------- Phase 2: GEMM over 4 N-tiles ---------------------------
    const __half* __restrict__ B = g_wh;     // [512,512] row-major [n][k]
    const int g  = lane >> 2;
    const int tg = lane & 3;
    const int wm = warp >> 2;   // 0..1
    const int wn = warp & 3;    // 0..3

    uint32_t sB0 = (uint32_t)__cvta_generic_to_shared(Bs0);
    uint32_t sB1 = (uint32_t)__cvta_generic_to_shared(Bs1);

#define ISSUE_B(buf, n0, k0)                                                         \
    do {                                                                             \
        uint32_t sb = (buf) ? sB1 : sB0;                                             \
        _Pragma("unroll")                                                            \
        for (int i = 0; i < 2; i++) {                                                \
            int idx = i * 256 + tid;                                                 \
            int row = idx >> 2, c8 = idx & 3;                                        \
            const __half* gp = B + (size_t)((n0) + row) * D + (k0) + c8 * 8;         \
            cp_async16(sb + (row * HPITCH + c8 * 8) * 2, gp, 1);                     \
        }                                                                            \
    } while (0)

    const int NCHUNK = D / KC;   // 16

    for (int nt = 0; nt < 4; nt++) {
        const int n0 = nt * 128;

        float acc[4][4][4];
#pragma unroll
        for (int i = 0; i < 4; i++)
#pragma unroll
            for (int jj = 0; jj < 4; jj++)
#pragma unroll
                for (int r = 0; r < 4; r++) acc[i][jj][r] = 0.f;

        ISSUE_B(0, n0, 0);
        cp_commit();

        for (int kc = 0; kc < NCHUNK; kc++) {
            int buf = kc & 1;
            if (kc + 1 < NCHUNK) {
                ISSUE_B((kc + 1) & 1, n0, (kc + 1) * KC);
                cp_commit();
                cp_wait1();
            } else {
                cp_wait0();
            }
            __syncthreads();

            const __half* bs = buf ? Bs1 : Bs0;
            const int kbase = kc * KC;

#pragma unroll
            for (int ks = 0; ks < 2; ks++) {
                int kkg = kbase + ks * 16;   // global k for A
                int kk  = ks * 16;           // local k for B chunk
                uint32_t af[4][4], bf[4][2];
#pragma unroll
                for (int mi = 0; mi < 4; mi++) {
                    int rb = wm * 64 + mi * 16;
                    af[mi][0] = *(const uint32_t*)(sA + (rb + g)     * APITCH + kkg + 2 * tg);
                    af[mi][1] = *(const uint32_t*)(sA + (rb + g + 8) * APITCH + kkg + 2 * tg);
                    af[mi][2] = *(const uint32_t*)(sA + (rb + g)     * APITCH + kkg + 2 * tg + 8);
                    af[mi][3] = *(const uint32_t*)(sA + (rb + g + 8) * APITCH + kkg + 2 * tg + 8);
                }
#pragma unroll
                for (int nj = 0; nj < 4; nj++) {
                    int nb = wn * 32 + nj * 8;
                    bf[nj][0] = *(const uint32_t*)(bs + (nb + g) * HPITCH + kk + 2 * tg);
                    bf[nj][1] = *(const uint32_t*)(bs + (nb + g) * HPITCH + kk + 2 * tg + 8);
                }
#pragma unroll
                for (int mi = 0; mi < 4; mi++)
#pragma unroll
                    for (int nj = 0; nj < 4; nj++) {
                        asm volatile(
                            "mma.sync.aligned.m16n8k16.row.col.f32.f16.f16.f32 "
                            "{%0,%1,%2,%3}, {%4,%5,%6,%7}, {%8,%9}, {%0,%1,%2,%3};"
                            : "+f"(acc[mi][nj][0]), "+f"(acc[mi][nj][1]),
                              "+f"(acc[mi][nj][2]), "+f"(acc[mi][nj][3])
                            : "r"(af[mi][0]), "r"(af[mi][1]), "r"(af[mi][2]), "r"(af[mi][3]),
                              "r"(bf[nj][0]), "r"(bf[nj][1]));
                    }
            }
            __syncthreads();
        }

        // epilogue for this N-tile
#pragma unroll
        for (int mi = 0; mi < 4; mi++) {
            int r0 = m0 + wm * 64 + mi * 16 + g;
            int r1 = r0 + 8;
#pragma unroll
            for (int nj = 0; nj < 4; nj++) {
                int cn = n0 + wn * 32 + nj * 8 + 2 * tg;
                float2 bb = *(const float2*)(bias + cn);
                if (r0 < Nrows) {
                    float2 v = make_float2(acc[mi][nj][0] + bb.x, acc[mi][nj][1] + bb.y);
                    *(float2*)(out + (size_t)r0 * D + cn) = v;
                }
                if (r1 < Nrows) {
                    float2 v = make_float2(acc[mi][nj][2] + bb.x, acc[mi][nj][3] + bb.y);
                    *(float2*)(out + (size_t)r1 * D + cn) = v;
                }
            }
        }
    }
#undef ISSUE_B
}

// ---------------- launch ----------------
extern "C" void kernel_launch(void* const* d_in, const int* in_sizes, int n_in,
                              void* d_out, int out_size) {
    const float* x         = (const float*)d_in[0];
    const void*  ei        = d_in[1];
    const float* edge_attr = (const float*)d_in[2];
    const float* lin_w     = (const float*)d_in[3];
    const float* lin_b     = (const float*)d_in[4];
    const float* conf_w    = (const float*)d_in[5];
    const float* conf_b    = (const float*)d_in[6];
    float* out             = (float*)d_out;

    const int n_nodes = in_sizes[0] / D;
    const int E       = in_sizes[2] / 3;
    const int nb      = (n_nodes + 1023) / 1024;
    const int eblocks = (E + 255) / 256;
    const int convblocks = 1024;

    static int smem_set = 0;
    if (!smem_set) {
        cudaFuncSetAttribute(agg_gemm_kernel,
                             cudaFuncAttributeMaxDynamicSharedMemorySize, FSMEM);
        smem_set = 1;
    }

    zero_small_kernel<<<(n_nodes + 255) / 256, 256>>>(n_nodes);

    histconv_kernel<<<eblocks + convblocks, 256>>>(ei, x, lin_w, E, n_nodes,
                                                   eblocks, convblocks);

    scanAB_kernel<<<nb, 1024>>>(n_nodes, nb);

    fill_kernel<<<eblocks, 256>>>(ei, edge_attr, conf_w, conf_b, E);

    {
        int blocks = (n_nodes + 127) / 128;
        agg_gemm_kernel<<<blocks, 256, FSMEM>>>(lin_b, out, n_nodes);
    }
}

// round 15
// speedup vs baseline: 1.6996x; 1.6996x over previous
#include <cuda_runtime.h>
#include <cuda_fp16.h>
#include <cstdint>

#define D        512
#define MAXN     50000
#define MAXE     800000
#define SCANB    ((MAXN + 1023) / 1024)   // 49 blocks

// ---------------- device scratch ----------------
__device__ __half g_aggh[(size_t)MAXN * D]; // aggregated messages [N, 512] fp16
__device__ __half g_xh[(size_t)MAXN * D];   // x converted to fp16
__device__ __half g_wh[(size_t)D * D];      // W converted to fp16 [n][k]
__device__ float  g_deg[MAXN];              // source-degree
__device__ int    g_cnt[MAXN];              // col histogram
__device__ int    g_off[MAXN + 1];          // CSC partial offsets (scanA output)
__device__ int    g_cur[MAXN];              // fill cursors
__device__ int2   g_spack[MAXE];            // packed (srow, norm-bits) by destination
__device__ int    g_bsum[SCANB];
__device__ int    g_boff[SCANB];            // per-block exclusive offsets
__device__ int    g_done;                   // scan last-block arrival counter

// ---------------- inline dtype sniff ----------------
__device__ __forceinline__ int sniff_is64(const int* ei32) {
    int lane = threadIdx.x & 31;
    int v = ei32[2 * lane + 1];
    unsigned nz = __ballot_sync(0xffffffffu, v != 0);
    return nz == 0u;
}

__device__ __forceinline__ int load_idx(const void* ei, long long pos, int is64) {
    if (is64) return (int)((const long long*)ei)[pos];
    return ((const int*)ei)[pos];
}

__device__ __forceinline__ int final_off(int i) {
    return (i == 0) ? 0 : (g_off[i] + g_boff[(i - 1) >> 10]);
}

// ---------------- zero small arrays ----------------
__global__ void zero_small_kernel(int n_nodes) {
    int i = blockIdx.x * blockDim.x + threadIdx.x;
    if (i < n_nodes) {
        g_deg[i] = 0.f;
        g_cnt[i] = 0;
        g_cur[i] = 0;
    }
    if (i == 0) g_done = 0;
}

// ---------------- fused histogram + fp16 conversions (block-range split) ----
__global__ void __launch_bounds__(256)
histconv_kernel(const void* __restrict__ ei,
                const float* __restrict__ x,
                const float* __restrict__ W,
                int E, int n_nodes, int eblocks, int convblocks) {
    if ((int)blockIdx.x < eblocks) {
        int is64 = sniff_is64((const int*)ei);
        int e = blockIdx.x * 256 + threadIdx.x;
        if (e >= E) return;
        int r = load_idx(ei, e, is64);
        int c = load_idx(ei, (long long)E + e, is64);
        atomicAdd(&g_deg[r], 1.0f);
        atomicAdd(&g_cnt[c], 1);
    } else {
        size_t t = (size_t)(blockIdx.x - eblocks) * 256 + threadIdx.x;
        size_t stride = (size_t)convblocks * 256;

        size_t wtotal8 = (size_t)D * D / 8;
        for (size_t k = t; k < wtotal8; k += stride) {
            float4 f0 = ((const float4*)W)[2 * k];
            float4 f1 = ((const float4*)W)[2 * k + 1];
            __half2 h0 = __floats2half2_rn(f0.x, f0.y);
            __half2 h1 = __floats2half2_rn(f0.z, f0.w);
            __half2 h2 = __floats2half2_rn(f1.x, f1.y);
            __half2 h3 = __floats2half2_rn(f1.z, f1.w);
            uint4 p;
            p.x = *(uint32_t*)&h0; p.y = *(uint32_t*)&h1;
            p.z = *(uint32_t*)&h2; p.w = *(uint32_t*)&h3;
            ((uint4*)g_wh)[k] = p;
        }

        size_t xtotal8 = (size_t)n_nodes * D / 8;
        for (size_t k = t; k < xtotal8; k += stride) {
            float4 f0 = ((const float4*)x)[2 * k];
            float4 f1 = ((const float4*)x)[2 * k + 1];
            __half2 h0 = __floats2half2_rn(f0.x, f0.y);
            __half2 h1 = __floats2half2_rn(f0.z, f0.w);
            __half2 h2 = __floats2half2_rn(f1.x, f1.y);
            __half2 h3 = __floats2half2_rn(f1.z, f1.w);
            uint4 p;
            p.x = *(uint32_t*)&h0; p.y = *(uint32_t*)&h1;
            p.z = *(uint32_t*)&h2; p.w = *(uint32_t*)&h3;
            ((uint4*)g_xh)[k] = p;
        }
    }
}

// ---------------- scan: phase A per-block + fused phase B in last block -----
__device__ __forceinline__ int block_scan_1024(int v, int* warpsum) {
    const int lane = threadIdx.x & 31;
    const int wid  = threadIdx.x >> 5;
#pragma unroll
    for (int d = 1; d < 32; d <<= 1) {
        int tt = __shfl_up_sync(0xffffffffu, v, d);
        if (lane >= d) v += tt;
    }
    if (lane == 31) warpsum[wid] = v;
    __syncthreads();
    if (wid == 0) {
        int s = warpsum[lane];
#pragma unroll
        for (int d = 1; d < 32; d <<= 1) {
            int tt = __shfl_up_sync(0xffffffffu, s, d);
            if (lane >= d) s += tt;
        }
        warpsum[lane] = s;
    }
    __syncthreads();
    return v + ((wid > 0) ? warpsum[wid - 1] : 0);
}

__global__ void __launch_bounds__(1024)
scanAB_kernel(int n, int nb) {
    __shared__ int warpsum[32];
    __shared__ int is_last;
    int i = blockIdx.x * 1024 + threadIdx.x;
    int v = (i < n) ? g_cnt[i] : 0;
    int incl = block_scan_1024(v, warpsum);
    if (i < n) g_off[i + 1] = incl;
    if (i == 0) g_off[0] = 0;

    if (threadIdx.x == 1023) {
        g_bsum[blockIdx.x] = incl;
        __threadfence();
        int prev = atomicAdd(&g_done, 1);
        is_last = (prev == nb - 1);
    }
    __syncthreads();

    if (is_last) {
        __threadfence();
        int vv = (threadIdx.x < nb) ? g_bsum[threadIdx.x] : 0;
        int inc2 = block_scan_1024(vv, warpsum);
        if (threadIdx.x < nb) g_boff[threadIdx.x] = inc2 - vv;
        if (threadIdx.x == 0) g_done = 0;
    }
}

// ---------------- fused fill (packed int2 store) ----------------
__global__ void fill_kernel(const void* __restrict__ ei,
                            const float* __restrict__ edge_attr,
                            const float* __restrict__ conf_w,
                            const float* __restrict__ conf_b,
                            int E) {
    int is64 = sniff_is64((const int*)ei);
    int e = blockIdx.x * blockDim.x + threadIdx.x;
    if (e >= E) return;
    int r = load_idx(ei, e, is64);
    int c = load_idx(ei, (long long)E + e, is64);

    float z = edge_attr[3 * e + 0] * conf_w[0]
            + edge_attr[3 * e + 1] * conf_w[1]
            + edge_attr[3 * e + 2] * conf_w[2]
            + conf_b[0];
    float ew = 1.0f / (1.0f + expf(-z));

    float dr = g_deg[r];
    float dc = g_deg[c];
    float ir = (dr > 0.f) ? rsqrtf(dr) : 0.f;
    float ic = (dc > 0.f) ? rsqrtf(dc) : 0.f;
    float nrm = ir * ic * ew;
    if (isnan(nrm)) nrm = 0.f;

    int pos = final_off(c) + atomicAdd(&g_cur[c], 1);
    g_spack[pos] = make_int2(r, __float_as_int(nrm));
}

// ---------------- aggregate (fp16 gather, fp32 accumulate, fp16 out) --------
// One warp per destination node, 4-edge ILP (16 LDG.128 in flight per iter).
__device__ __forceinline__ void acc_u4(float2* a, uint4 u, float n) {
    const __half2* h = (const __half2*)&u;
#pragma unroll
    for (int j = 0; j < 4; j++) {
        float2 f = __half22float2(h[j]);
        a[j].x = fmaf(f.x, n, a[j].x);
        a[j].y = fmaf(f.y, n, a[j].y);
    }
}

__global__ void __launch_bounds__(256)
aggregate_kernel(int n_nodes) {
    int node = (blockIdx.x * blockDim.x + threadIdx.x) >> 5;
    int lane = threadIdx.x & 31;
    if (node >= n_nodes) return;

    int beg = final_off(node);
    int end = final_off(node + 1);

    float2 a[8];
#pragma unroll
    for (int j = 0; j < 8; j++) a[j] = make_float2(0.f, 0.f);

    int i = beg;
    // 4-edge unrolled main loop
    for (; i + 3 < end; i += 4) {
        int2 p0 = g_spack[i];
        int2 p1 = g_spack[i + 1];
        int2 p2 = g_spack[i + 2];
        int2 p3 = g_spack[i + 3];
        float n0 = __int_as_float(p0.y);
        float n1 = __int_as_float(p1.y);
        float n2 = __int_as_float(p2.y);
        float n3 = __int_as_float(p3.y);
        const uint4* x0 = (const uint4*)(g_xh + (size_t)p0.x * D);
        const uint4* x1 = (const uint4*)(g_xh + (size_t)p1.x * D);
        const uint4* x2 = (const uint4*)(g_xh + (size_t)p2.x * D);
        const uint4* x3 = (const uint4*)(g_xh + (size_t)p3.x * D);
        uint4 u00 = x0[lane];      uint4 u01 = x0[lane + 32];
        uint4 u10 = x1[lane];      uint4 u11 = x1[lane + 32];
        uint4 u20 = x2[lane];      uint4 u21 = x2[lane + 32];
        uint4 u30 = x3[lane];      uint4 u31 = x3[lane + 32];
        acc_u4(a,     u00, n0);    acc_u4(a + 4, u01, n0);
        acc_u4(a,     u10, n1);    acc_u4(a + 4, u11, n1);
        acc_u4(a,     u20, n2);    acc_u4(a + 4, u21, n2);
        acc_u4(a,     u30, n3);    acc_u4(a + 4, u31, n3);
    }
    // 2-edge tail
    for (; i + 1 < end; i += 2) {
        int2 pA = g_spack[i];
        int2 pB = g_spack[i + 1];
        float nA = __int_as_float(pA.y);
        float nB = __int_as_float(pB.y);
        const uint4* xA = (const uint4*)(g_xh + (size_t)pA.x * D);
        const uint4* xB = (const uint4*)(g_xh + (size_t)pB.x * D);
        uint4 uA0 = xA[lane];
        uint4 uA1 = xA[lane + 32];
        uint4 uB0 = xB[lane];
        uint4 uB1 = xB[lane + 32];
        acc_u4(a,     uA0, nA);
        acc_u4(a + 4, uA1, nA);
        acc_u4(a,     uB0, nB);
        acc_u4(a + 4, uB1, nB);
    }
    if (i < end) {
        int2 p = g_spack[i];
        float nm = __int_as_float(p.y);
        const uint4* xr = (const uint4*)(g_xh + (size_t)p.x * D);
        uint4 u0 = xr[lane];
        uint4 u1 = xr[lane + 32];
        acc_u4(a,     u0, nm);
        acc_u4(a + 4, u1, nm);
    }

    uint4* dst = (uint4*)(g_aggh + (size_t)node * D);
    uint4 o0, o1;
    __half2 t;
    t = __floats2half2_rn(a[0].x, a[0].y); o0.x = *(uint32_t*)&t;
    t = __floats2half2_rn(a[1].x, a[1].y); o0.y = *(uint32_t*)&t;
    t = __floats2half2_rn(a[2].x, a[2].y); o0.z = *(uint32_t*)&t;
    t = __floats2half2_rn(a[3].x, a[3].y); o0.w = *(uint32_t*)&t;
    t = __floats2half2_rn(a[4].x, a[4].y); o1.x = *(uint32_t*)&t;
    t = __floats2half2_rn(a[5].x, a[5].y); o1.y = *(uint32_t*)&t;
    t = __floats2half2_rn(a[6].x, a[6].y); o1.z = *(uint32_t*)&t;
    t = __floats2half2_rn(a[7].x, a[7].y); o1.w = *(uint32_t*)&t;
    dst[lane]      = o0;
    dst[lane + 32] = o1;
}

// ---------------- FP16 tensor-core GEMM: out = aggh @ Wh^T + b --------------
// Dynamic smem + launch_bounds(256,2) so 2 CTAs co-reside per SM.
#define KC       32
#define HPITCH   40
#define GSMEM    (2 * 128 * HPITCH * 2 * 2)   // 40960 B

__device__ __forceinline__ void cp_async16(uint32_t smem, const void* gptr, int valid) {
    asm volatile("cp.async.cg.shared.global [%0], [%1], 16, %2;\n"
                 :: "r"(smem), "l"(gptr), "r"(valid ? 16 : 0));
}
__device__ __forceinline__ void cp_commit() {
    asm volatile("cp.async.commit_group;\n" ::: "memory");
}
__device__ __forceinline__ void cp_wait1() {
    asm volatile("cp.async.wait_group 1;\n" ::: "memory");
}

__global__ void __launch_bounds__(256, 2)
gemm_fp16_kernel(const float* __restrict__ bias,
                 float* __restrict__ out,
                 int Nrows) {
    const __half* __restrict__ A = g_aggh;   // [N, 512]
    const __half* __restrict__ B = g_wh;     // [512, 512] row-major [n][k]

    extern __shared__ __half sdyn[];
    __half* As0 = sdyn;
    __half* As1 = As0 + 128 * HPITCH;
    __half* Bs0 = As1 + 128 * HPITCH;
    __half* Bs1 = Bs0 + 128 * HPITCH;

    const int tid  = threadIdx.x;
    const int warp = tid >> 5;
    const int lane = tid & 31;
    const int g    = lane >> 2;
    const int tg   = lane & 3;
    const int wm   = warp >> 2;
    const int wn   = warp & 3;
    const int m0   = blockIdx.x * 128;
    const int n0   = blockIdx.y * 128;

    float acc[4][4][4];
#pragma unroll
    for (int i = 0; i < 4; i++)
#pragma unroll
        for (int j = 0; j < 4; j++)
#pragma unroll
            for (int r = 0; r < 4; r++) acc[i][j][r] = 0.f;

    uint32_t sA0 = (uint32_t)__cvta_generic_to_shared(As0);
    uint32_t sA1 = (uint32_t)__cvta_generic_to_shared(As1);
    uint32_t sB0 = (uint32_t)__cvta_generic_to_shared(Bs0);
    uint32_t sB1 = (uint32_t)__cvta_generic_to_shared(Bs1);

#define ISSUE_TILE(buf, k0)                                                          \
    do {                                                                             \
        uint32_t sa = (buf) ? sA1 : sA0;                                             \
        uint32_t sb = (buf) ? sB1 : sB0;                                             \
        _Pragma("unroll")                                                            \
        for (int i = 0; i < 2; i++) {                                                \
            int idx = i * 256 + tid;                                                 \
            int row = idx >> 2, c8 = idx & 3;                                        \
            int grow = m0 + row;                                                     \
            const __half* gp = A + (size_t)grow * D + (k0) + c8 * 8;                 \
            cp_async16(sa + (row * HPITCH + c8 * 8) * 2, gp, grow < Nrows);          \
        }                                                                            \
        _Pragma("unroll")                                                            \
        for (int i = 0; i < 2; i++) {                                                \
            int idx = i * 256 + tid;                                                 \
            int row = idx >> 2, c8 = idx & 3;                                        \
            const __half* gp = B + (size_t)(n0 + row) * D + (k0) + c8 * 8;           \
            cp_async16(sb + (row * HPITCH + c8 * 8) * 2, gp, 1);                     \
        }                                                                            \
    } while (0)

    ISSUE_TILE(0, 0);
    cp_commit();

    const int NCHUNK = D / KC;   // 16
    for (int kc = 0; kc < NCHUNK; kc++) {
        int buf = kc & 1;
        if (kc + 1 < NCHUNK) ISSUE_TILE((kc + 1) & 1, (kc + 1) * KC);
        cp_commit();
        cp_wait1();
        __syncthreads();

        const __half* as = buf ? As1 : As0;
        const __half* bs = buf ? Bs1 : Bs0;

#pragma unroll
        for (int ks = 0; ks < 2; ks++) {
            int kk = ks * 16;
            uint32_t af[4][4], bf[4][2];
#pragma unroll
            for (int mi = 0; mi < 4; mi++) {
                int rb = wm * 64 + mi * 16;
                af[mi][0] = *(const uint32_t*)(as + (rb + g)     * HPITCH + kk + 2 * tg);
                af[mi][1] = *(const uint32_t*)(as + (rb + g + 8) * HPITCH + kk + 2 * tg);
                af[mi][2] = *(const uint32_t*)(as + (rb + g)     * HPITCH + kk + 2 * tg + 8);
                af[mi][3] = *(const uint32_t*)(as + (rb + g + 8) * HPITCH + kk + 2 * tg + 8);
            }
#pragma unroll
            for (int nj = 0; nj < 4; nj++) {
                int nb = wn * 32 + nj * 8;
                bf[nj][0] = *(const uint32_t*)(bs + (nb + g) * HPITCH + kk + 2 * tg);
                bf[nj][1] = *(const uint32_t*)(bs + (nb + g) * HPITCH + kk + 2 * tg + 8);
            }
#pragma unroll
            for (int mi = 0; mi < 4; mi++)
#pragma unroll
                for (int nj = 0; nj < 4; nj++) {
                    asm volatile(
                        "mma.sync.aligned.m16n8k16.row.col.f32.f16.f16.f32 "
                        "{%0,%1,%2,%3}, {%4,%5,%6,%7}, {%8,%9}, {%0,%1,%2,%3};"
                        : "+f"(acc[mi][nj][0]), "+f"(acc[mi][nj][1]),
                          "+f"(acc[mi][nj][2]), "+f"(acc[mi][nj][3])
                        : "r"(af[mi][0]), "r"(af[mi][1]), "r"(af[mi][2]), "r"(af[mi][3]),
                          "r"(bf[nj][0]), "r"(bf[nj][1]));
                }
        }
        __syncthreads();
    }

#pragma unroll
    for (int mi = 0; mi < 4; mi++) {
        int r0 = m0 + wm * 64 + mi * 16 + g;
        int r1 = r0 + 8;
#pragma unroll
        for (int nj = 0; nj < 4; nj++) {
            int cn = n0 + wn * 32 + nj * 8 + 2 * tg;
            float2 bb = *(const float2*)(bias + cn);
            if (r0 < Nrows) {
                float2 v = make_float2(acc[mi][nj][0] + bb.x, acc[mi][nj][1] + bb.y);
                *(float2*)(out + (size_t)r0 * D + cn) = v;
            }
            if (r1 < Nrows) {
                float2 v = make_float2(acc[mi][nj][2] + bb.x, acc[mi][nj][3] + bb.y);
                *(float2*)(out + (size_t)r1 * D + cn) = v;
            }
        }
    }
#undef ISSUE_TILE
}

// ---------------- launch ----------------
extern "C" void kernel_launch(void* const* d_in, const int* in_sizes, int n_in,
                              void* d_out, int out_size) {
    const float* x         = (const float*)d_in[0];
    const void*  ei        = d_in[1];
    const float* edge_attr = (const float*)d_in[2];
    const float* lin_w     = (const float*)d_in[3];
    const float* lin_b     = (const float*)d_in[4];
    const float* conf_w    = (const float*)d_in[5];
    const float* conf_b    = (const float*)d_in[6];
    float* out             = (float*)d_out;

    const int n_nodes = in_sizes[0] / D;
    const int E       = in_sizes[2] / 3;
    const int nb      = (n_nodes + 1023) / 1024;
    const int eblocks = (E + 255) / 256;
    const int convblocks = 1024;

    static int smem_set = 0;
    if (!smem_set) {
        cudaFuncSetAttribute(gemm_fp16_kernel,
                             cudaFuncAttributeMaxDynamicSharedMemorySize, GSMEM);
        smem_set = 1;
    }

    zero_small_kernel<<<(n_nodes + 255) / 256, 256>>>(n_nodes);

    histconv_kernel<<<eblocks + convblocks, 256>>>(ei, x, lin_w, E, n_nodes,
                                                   eblocks, convblocks);

    scanAB_kernel<<<nb, 1024>>>(n_nodes, nb);

    fill_kernel<<<eblocks, 256>>>(ei, edge_attr, conf_w, conf_b, E);

    {
        int warps_per_block = 256 / 32;
        int blocks = (n_nodes + warps_per_block - 1) / warps_per_block;
        aggregate_kernel<<<blocks, 256>>>(n_nodes);
    }

    {
        dim3 grid((n_nodes + 127) / 128, D / 128);
        gemm_fp16_kernel<<<grid, 256, GSMEM>>>(lin_b, out, n_nodes);
    }
}

// round 16
// speedup vs baseline: 1.7805x; 1.0476x over previous
#include <cuda_runtime.h>
#include <cuda_fp16.h>
#include <cstdint>

#define D        512
#define MAXN     50000
#define MAXE     800000
#define SCANB    ((MAXN + 1023) / 1024)   // 49 blocks

// ---------------- device scratch ----------------
__device__ __half g_aggh[(size_t)MAXN * D]; // aggregated messages [N, 512] fp16
__device__ __half g_xh[(size_t)MAXN * D];   // x converted to fp16
__device__ __half g_wh[(size_t)D * D];      // W converted to fp16 [n][k]
__device__ float  g_deg[MAXN];              // source-degree
__device__ int    g_cnt[MAXN];              // col histogram
__device__ int    g_off[MAXN + 1];          // CSC partial offsets (scanA output)
__device__ int    g_cur[MAXN];              // fill cursors
__device__ int2   g_spack[MAXE];            // packed (srow, norm-bits) by destination
__device__ int    g_bsum[SCANB];
__device__ int    g_boff[SCANB];            // per-block exclusive offsets
__device__ int    g_done;                   // scan last-block arrival counter

// ---------------- inline dtype sniff ----------------
__device__ __forceinline__ int sniff_is64(const int* ei32) {
    int lane = threadIdx.x & 31;
    int v = ei32[2 * lane + 1];
    unsigned nz = __ballot_sync(0xffffffffu, v != 0);
    return nz == 0u;
}

__device__ __forceinline__ int load_idx(const void* ei, long long pos, int is64) {
    if (is64) return (int)((const long long*)ei)[pos];
    return ((const int*)ei)[pos];
}

__device__ __forceinline__ int final_off(int i) {
    return (i == 0) ? 0 : (g_off[i] + g_boff[(i - 1) >> 10]);
}

// ---------------- zero small arrays ----------------
__global__ void zero_small_kernel(int n_nodes) {
    int i = blockIdx.x * blockDim.x + threadIdx.x;
    if (i < n_nodes) {
        g_deg[i] = 0.f;
        g_cnt[i] = 0;
        g_cur[i] = 0;
    }
    if (i == 0) g_done = 0;
}

// ---------------- fused histogram + fp16 conversions (block-range split) ----
__global__ void __launch_bounds__(256)
histconv_kernel(const void* __restrict__ ei,
                const float* __restrict__ x,
                const float* __restrict__ W,
                int E, int n_nodes, int eblocks, int convblocks) {
    if ((int)blockIdx.x < eblocks) {
        int is64 = sniff_is64((const int*)ei);
        int e = blockIdx.x * 256 + threadIdx.x;
        if (e >= E) return;
        int r = load_idx(ei, e, is64);
        int c = load_idx(ei, (long long)E + e, is64);
        atomicAdd(&g_deg[r], 1.0f);
        atomicAdd(&g_cnt[c], 1);
    } else {
        size_t t = (size_t)(blockIdx.x - eblocks) * 256 + threadIdx.x;
        size_t stride = (size_t)convblocks * 256;

        size_t wtotal8 = (size_t)D * D / 8;
        for (size_t k = t; k < wtotal8; k += stride) {
            float4 f0 = ((const float4*)W)[2 * k];
            float4 f1 = ((const float4*)W)[2 * k + 1];
            __half2 h0 = __floats2half2_rn(f0.x, f0.y);
            __half2 h1 = __floats2half2_rn(f0.z, f0.w);
            __half2 h2 = __floats2half2_rn(f1.x, f1.y);
            __half2 h3 = __floats2half2_rn(f1.z, f1.w);
            uint4 p;
            p.x = *(uint32_t*)&h0; p.y = *(uint32_t*)&h1;
            p.z = *(uint32_t*)&h2; p.w = *(uint32_t*)&h3;
            ((uint4*)g_wh)[k] = p;
        }

        size_t xtotal8 = (size_t)n_nodes * D / 8;
        for (size_t k = t; k < xtotal8; k += stride) {
            float4 f0 = ((const float4*)x)[2 * k];
            float4 f1 = ((const float4*)x)[2 * k + 1];
            __half2 h0 = __floats2half2_rn(f0.x, f0.y);
            __half2 h1 = __floats2half2_rn(f0.z, f0.w);
            __half2 h2 = __floats2half2_rn(f1.x, f1.y);
            __half2 h3 = __floats2half2_rn(f1.z, f1.w);
            uint4 p;
            p.x = *(uint32_t*)&h0; p.y = *(uint32_t*)&h1;
            p.z = *(uint32_t*)&h2; p.w = *(uint32_t*)&h3;
            ((uint4*)g_xh)[k] = p;
        }
    }
}

// ---------------- scan: phase A per-block + fused phase B in last block -----
__device__ __forceinline__ int block_scan_1024(int v, int* warpsum) {
    const int lane = threadIdx.x & 31;
    const int wid  = threadIdx.x >> 5;
#pragma unroll
    for (int d = 1; d < 32; d <<= 1) {
        int tt = __shfl_up_sync(0xffffffffu, v, d);
        if (lane >= d) v += tt;
    }
    if (lane == 31) warpsum[wid] = v;
    __syncthreads();
    if (wid == 0) {
        int s = warpsum[lane];
#pragma unroll
        for (int d = 1; d < 32; d <<= 1) {
            int tt = __shfl_up_sync(0xffffffffu, s, d);
            if (lane >= d) s += tt;
        }
        warpsum[lane] = s;
    }
    __syncthreads();
    return v + ((wid > 0) ? warpsum[wid - 1] : 0);
}

__global__ void __launch_bounds__(1024)
scanAB_kernel(int n, int nb) {
    __shared__ int warpsum[32];
    __shared__ int is_last;
    int i = blockIdx.x * 1024 + threadIdx.x;
    int v = (i < n) ? g_cnt[i] : 0;
    int incl = block_scan_1024(v, warpsum);
    if (i < n) g_off[i + 1] = incl;
    if (i == 0) g_off[0] = 0;

    if (threadIdx.x == 1023) {
        g_bsum[blockIdx.x] = incl;
        __threadfence();
        int prev = atomicAdd(&g_done, 1);
        is_last = (prev == nb - 1);
    }
    __syncthreads();

    if (is_last) {
        __threadfence();
        int vv = (threadIdx.x < nb) ? g_bsum[threadIdx.x] : 0;
        int inc2 = block_scan_1024(vv, warpsum);
        if (threadIdx.x < nb) g_boff[threadIdx.x] = inc2 - vv;
        if (threadIdx.x == 0) g_done = 0;
    }
}

// ---------------- fused fill (packed int2 store) ----------------
__global__ void fill_kernel(const void* __restrict__ ei,
                            const float* __restrict__ edge_attr,
                            const float* __restrict__ conf_w,
                            const float* __restrict__ conf_b,
                            int E) {
    int is64 = sniff_is64((const int*)ei);
    int e = blockIdx.x * blockDim.x + threadIdx.x;
    if (e >= E) return;
    int r = load_idx(ei, e, is64);
    int c = load_idx(ei, (long long)E + e, is64);

    float z = edge_attr[3 * e + 0] * conf_w[0]
            + edge_attr[3 * e + 1] * conf_w[1]
            + edge_attr[3 * e + 2] * conf_w[2]
            + conf_b[0];
    float ew = 1.0f / (1.0f + expf(-z));

    float dr = g_deg[r];
    float dc = g_deg[c];
    float ir = (dr > 0.f) ? rsqrtf(dr) : 0.f;
    float ic = (dc > 0.f) ? rsqrtf(dc) : 0.f;
    float nrm = ir * ic * ew;
    if (isnan(nrm)) nrm = 0.f;

    int pos = final_off(c) + atomicAdd(&g_cur[c], 1);
    g_spack[pos] = make_int2(r, __float_as_int(nrm));
}

// ---------------- aggregate (fp16 gather, fp32 accumulate, fp16 out) --------
// One warp per destination node, 2-edge ILP (best measured config).
__device__ __forceinline__ void acc_u4(float2* a, uint4 u, float n) {
    const __half2* h = (const __half2*)&u;
#pragma unroll
    for (int j = 0; j < 4; j++) {
        float2 f = __half22float2(h[j]);
        a[j].x = fmaf(f.x, n, a[j].x);
        a[j].y = fmaf(f.y, n, a[j].y);
    }
}

__global__ void __launch_bounds__(256)
aggregate_kernel(int n_nodes) {
    int node = (blockIdx.x * blockDim.x + threadIdx.x) >> 5;
    int lane = threadIdx.x & 31;
    if (node >= n_nodes) return;

    int beg = final_off(node);
    int end = final_off(node + 1);

    float2 a[8];
#pragma unroll
    for (int j = 0; j < 8; j++) a[j] = make_float2(0.f, 0.f);

    int i = beg;
    for (; i + 1 < end; i += 2) {
        int2 pA = g_spack[i];
        int2 pB = g_spack[i + 1];
        float nA = __int_as_float(pA.y);
        float nB = __int_as_float(pB.y);
        const uint4* xA = (const uint4*)(g_xh + (size_t)pA.x * D);
        const uint4* xB = (const uint4*)(g_xh + (size_t)pB.x * D);
        uint4 uA0 = xA[lane];
        uint4 uA1 = xA[lane + 32];
        uint4 uB0 = xB[lane];
        uint4 uB1 = xB[lane + 32];
        acc_u4(a,     uA0, nA);
        acc_u4(a + 4, uA1, nA);
        acc_u4(a,     uB0, nB);
        acc_u4(a + 4, uB1, nB);
    }
    if (i < end) {
        int2 p = g_spack[i];
        float nm = __int_as_float(p.y);
        const uint4* xr = (const uint4*)(g_xh + (size_t)p.x * D);
        uint4 u0 = xr[lane];
        uint4 u1 = xr[lane + 32];
        acc_u4(a,     u0, nm);
        acc_u4(a + 4, u1, nm);
    }

    uint4* dst = (uint4*)(g_aggh + (size_t)node * D);
    uint4 o0, o1;
    __half2 t;
    t = __floats2half2_rn(a[0].x, a[0].y); o0.x = *(uint32_t*)&t;
    t = __floats2half2_rn(a[1].x, a[1].y); o0.y = *(uint32_t*)&t;
    t = __floats2half2_rn(a[2].x, a[2].y); o0.z = *(uint32_t*)&t;
    t = __floats2half2_rn(a[3].x, a[3].y); o0.w = *(uint32_t*)&t;
    t = __floats2half2_rn(a[4].x, a[4].y); o1.x = *(uint32_t*)&t;
    t = __floats2half2_rn(a[5].x, a[5].y); o1.y = *(uint32_t*)&t;
    t = __floats2half2_rn(a[6].x, a[6].y); o1.z = *(uint32_t*)&t;
    t = __floats2half2_rn(a[7].x, a[7].y); o1.w = *(uint32_t*)&t;
    dst[lane]      = o0;
    dst[lane + 32] = o1;
}

// ---------------- FP16 tensor-core GEMM: out = aggh @ Wh^T + b --------------
// Block tile 128x128, 256 threads (8 warps as 2x4), warp tile 64x32.
// K-chunk 64 (halves the sync count), double buffered, 2 CTAs/SM.
// Streaming stores for the output (write-once, keep L2 for A re-reads).
#define KC       64
#define HPITCH   72                          // 64 data + 8 pad; 36-word pitch conflict-free
#define GSMEM    (4 * 128 * HPITCH * 2)      // A0,A1,B0,B1 = 73728 B

__device__ __forceinline__ void cp_async16(uint32_t smem, const void* gptr, int valid) {
    asm volatile("cp.async.cg.shared.global [%0], [%1], 16, %2;\n"
                 :: "r"(smem), "l"(gptr), "r"(valid ? 16 : 0));
}
__device__ __forceinline__ void cp_commit() {
    asm volatile("cp.async.commit_group;\n" ::: "memory");
}
__device__ __forceinline__ void cp_wait1() {
    asm volatile("cp.async.wait_group 1;\n" ::: "memory");
}
__device__ __forceinline__ void cp_wait0() {
    asm volatile("cp.async.wait_group 0;\n" ::: "memory");
}

__global__ void __launch_bounds__(256, 2)
gemm_fp16_kernel(const float* __restrict__ bias,
                 float* __restrict__ out,
                 int Nrows) {
    const __half* __restrict__ A = g_aggh;   // [N, 512]
    const __half* __restrict__ B = g_wh;     // [512, 512] row-major [n][k]

    extern __shared__ __half sdyn[];
    __half* As0 = sdyn;
    __half* As1 = As0 + 128 * HPITCH;
    __half* Bs0 = As1 + 128 * HPITCH;
    __half* Bs1 = Bs0 + 128 * HPITCH;

    const int tid  = threadIdx.x;
    const int warp = tid >> 5;
    const int lane = tid & 31;
    const int g    = lane >> 2;
    const int tg   = lane & 3;
    const int wm   = warp >> 2;
    const int wn   = warp & 3;
    const int m0   = blockIdx.x * 128;
    const int n0   = blockIdx.y * 128;

    float acc[4][4][4];
#pragma unroll
    for (int i = 0; i < 4; i++)
#pragma unroll
        for (int j = 0; j < 4; j++)
#pragma unroll
            for (int r = 0; r < 4; r++) acc[i][j][r] = 0.f;

    uint32_t sA0 = (uint32_t)__cvta_generic_to_shared(As0);
    uint32_t sA1 = (uint32_t)__cvta_generic_to_shared(As1);
    uint32_t sB0 = (uint32_t)__cvta_generic_to_shared(Bs0);
    uint32_t sB1 = (uint32_t)__cvta_generic_to_shared(Bs1);

    // Per chunk: A 128x64 halves = 1024 16B chunks (4/thread); same for B.
#define ISSUE_TILE(buf, k0)                                                          \
    do {                                                                             \
        uint32_t sa = (buf) ? sA1 : sA0;                                             \
        uint32_t sb = (buf) ? sB1 : sB0;                                             \
        _Pragma("unroll")                                                            \
        for (int i = 0; i < 4; i++) {                                                \
            int idx = i * 256 + tid;                                                 \
            int row = idx >> 3, c8 = idx & 7;                                        \
            int grow = m0 + row;                                                     \
            const __half* gp = A + (size_t)grow * D + (k0) + c8 * 8;                 \
            cp_async16(sa + (row * HPITCH + c8 * 8) * 2, gp, grow < Nrows);          \
        }                                                                            \
        _Pragma("unroll")                                                            \
        for (int i = 0; i < 4; i++) {                                                \
            int idx = i * 256 + tid;                                                 \
            int row = idx >> 3, c8 = idx & 7;                                        \
            const __half* gp = B + (size_t)(n0 + row) * D + (k0) + c8 * 8;           \
            cp_async16(sb + (row * HPITCH + c8 * 8) * 2, gp, 1);                     \
        }                                                                            \
    } while (0)

    ISSUE_TILE(0, 0);
    cp_commit();

    const int NCHUNK = D / KC;   // 8
    for (int kc = 0; kc < NCHUNK; kc++) {
        int buf = kc & 1;
        if (kc + 1 < NCHUNK) {
            ISSUE_TILE((kc + 1) & 1, (kc + 1) * KC);
            cp_commit();
            cp_wait1();
        } else {
            cp_wait0();
        }
        __syncthreads();

        const __half* as = buf ? As1 : As0;
        const __half* bs = buf ? Bs1 : Bs0;

#pragma unroll
        for (int ks = 0; ks < 4; ks++) {
            int kk = ks * 16;
            uint32_t af[4][4], bf[4][2];
#pragma unroll
            for (int mi = 0; mi < 4; mi++) {
                int rb = wm * 64 + mi * 16;
                af[mi][0] = *(const uint32_t*)(as + (rb + g)     * HPITCH + kk + 2 * tg);
                af[mi][1] = *(const uint32_t*)(as + (rb + g + 8) * HPITCH + kk + 2 * tg);
                af[mi][2] = *(const uint32_t*)(as + (rb + g)     * HPITCH + kk + 2 * tg + 8);
                af[mi][3] = *(const uint32_t*)(as + (rb + g + 8) * HPITCH + kk + 2 * tg + 8);
            }
#pragma unroll
            for (int nj = 0; nj < 4; nj++) {
                int nb = wn * 32 + nj * 8;
                bf[nj][0] = *(const uint32_t*)(bs + (nb + g) * HPITCH + kk + 2 * tg);
                bf[nj][1] = *(const uint32_t*)(bs + (nb + g) * HPITCH + kk + 2 * tg + 8);
            }
#pragma unroll
            for (int mi = 0; mi < 4; mi++)
#pragma unroll
                for (int nj = 0; nj < 4; nj++) {
                    asm volatile(
                        "mma.sync.aligned.m16n8k16.row.col.f32.f16.f16.f32 "
                        "{%0,%1,%2,%3}, {%4,%5,%6,%7}, {%8,%9}, {%0,%1,%2,%3};"
                        : "+f"(acc[mi][nj][0]), "+f"(acc[mi][nj][1]),
                          "+f"(acc[mi][nj][2]), "+f"(acc[mi][nj][3])
                        : "r"(af[mi][0]), "r"(af[mi][1]), "r"(af[mi][2]), "r"(af[mi][3]),
                          "r"(bf[nj][0]), "r"(bf[nj][1]));
                }
        }
        __syncthreads();
    }

#pragma unroll
    for (int mi = 0; mi < 4; mi++) {
        int r0 = m0 + wm * 64 + mi * 16 + g;
        int r1 = r0 + 8;
#pragma unroll
        for (int nj = 0; nj < 4; nj++) {
            int cn = n0 + wn * 32 + nj * 8 + 2 * tg;
            float2 bb = *(const float2*)(bias + cn);
            if (r0 < Nrows) {
                float2 v = make_float2(acc[mi][nj][0] + bb.x, acc[mi][nj][1] + bb.y);
                __stcs((float2*)(out + (size_t)r0 * D + cn), v);
            }
            if (r1 < Nrows) {
                float2 v = make_float2(acc[mi][nj][2] + bb.x, acc[mi][nj][3] + bb.y);
                __stcs((float2*)(out + (size_t)r1 * D + cn), v);
            }
        }
    }
#undef ISSUE_TILE
}

// ---------------- launch ----------------
extern "C" void kernel_launch(void* const* d_in, const int* in_sizes, int n_in,
                              void* d_out, int out_size) {
    const float* x         = (const float*)d_in[0];
    const void*  ei        = d_in[1];
    const float* edge_attr = (const float*)d_in[2];
    const float* lin_w     = (const float*)d_in[3];
    const float* lin_b     = (const float*)d_in[4];
    const float* conf_w    = (const float*)d_in[5];
    const float* conf_b    = (const float*)d_in[6];
    float* out             = (float*)d_out;

    const int n_nodes = in_sizes[0] / D;
    const int E       = in_sizes[2] / 3;
    const int nb      = (n_nodes + 1023) / 1024;
    const int eblocks = (E + 255) / 256;
    const int convblocks = 1024;

    static int smem_set = 0;
    if (!smem_set) {
        cudaFuncSetAttribute(gemm_fp16_kernel,
                             cudaFuncAttributeMaxDynamicSharedMemorySize, GSMEM);
        smem_set = 1;
    }

    zero_small_kernel<<<(n_nodes + 255) / 256, 256>>>(n_nodes);

    histconv_kernel<<<eblocks + convblocks, 256>>>(ei, x, lin_w, E, n_nodes,
                                                   eblocks, convblocks);

    scanAB_kernel<<<nb, 1024>>>(n_nodes, nb);

    fill_kernel<<<eblocks, 256>>>(ei, edge_attr, conf_w, conf_b, E);

    {
        int warps_per_block = 256 / 32;
        int blocks = (n_nodes + warps_per_block - 1) / warps_per_block;
        aggregate_kernel<<<blocks, 256>>>(n_nodes);
    }

    {
        dim3 grid((n_nodes + 127) / 128, D / 128);
        gemm_fp16_kernel<<<grid, 256, GSMEM>>>(lin_b, out, n_nodes);
    }
}